// round 16
// baseline (speedup 1.0000x reference)
#include <cuda_runtime.h>

#define CC 8
#define NN 4096
#define NC (CC*NN)
#define KH 11
#define MAXDET 100
#define XBINS 768          // x1 in [-64, 704), 1px bins
#define XOFF 64
#define K1_TILE 32
#define K1_SUB 16
#define K1_SPAN 384
#define SKCAP 14336        // smem key staging capacity (keys)

// ---------------- scratch (device globals; no allocation) ----------------
__device__ int    g_m[CC];            // valid count per class
__device__ float4 g_sbox[NC];         // bin-sorted boxes (by slot)
__device__ float2 g_saux[NC];         // sorted aux: (area, orig idx as int bits)
__device__ int    g_rmin[NC];         // per sorted slot: min orig idx of hit (init self)
__device__ float  g_pavg[NC*12];
__device__ float  g_bavg[NC*4];
__device__ int    g_scount[CC];       // survivors per class
__device__ int    g_srow[NC];         // compacted survivor rows (ascending per class)
__device__ unsigned g_skey[NC];       // compacted survivor keys (monotone score bits)
__device__ int    g_sync;             // last-class-block counter for k5 (reset by k0)

// ---------------- shuffle-based inclusive block scan (blockDim.x == 1024) ----------------
__device__ __forceinline__ int blockScanInc(int v, int* ws) {
    const unsigned FULL = 0xFFFFFFFFu;
    int lane = threadIdx.x & 31, w = threadIdx.x >> 5;
#pragma unroll
    for (int o = 1; o < 32; o <<= 1) {
        int n = __shfl_up_sync(FULL, v, o);
        if (lane >= o) v += n;
    }
    if (lane == 31) ws[w] = v;
    __syncthreads();
    if (w == 0) {
        int s = ws[lane];
#pragma unroll
        for (int o = 1; o < 32; o <<= 1) {
            int n = __shfl_up_sync(FULL, s, o);
            if (lane >= o) s += n;
        }
        ws[lane] = s;
    }
    __syncthreads();
    int r = v + ((w > 0) ? ws[w - 1] : 0);
    __syncthreads();
    return r;
}

// ---------------- K0: per-class compact + counting sort (MLP-8 loads) ----------------
__global__ __launch_bounds__(1024) void k0_sort(const float* __restrict__ cls,
                                                const float* __restrict__ boxes) {
    __shared__ int hist[XBINS];
    __shared__ int sstart[XBINS];
    __shared__ int ws[32];
    int c = blockIdx.x;
    int t = threadIdx.x;

    if (c == 0 && t == 0) g_sync = 0;      // reset fusion counter each launch

    for (int b = t; b < XBINS; b += 1024) hist[b] = 0;
    __syncthreads();

    // issue all 8 loads (4 cls + 4 boxes) unconditionally -> full MLP
    float  sc4[4];
    float4 mybox[4];
#pragma unroll
    for (int u = 0; u < 4; u++) {
        int a = t + u * 1024;
        sc4[u]   = cls[a * CC + c];
        mybox[u] = *(const float4*)(boxes + (size_t)a * (CC * 4) + c * 4);
    }
    bool myv[4];
    int  mybin[4];
#pragma unroll
    for (int u = 0; u < 4; u++) {
        myv[u] = sc4[u] > 0.5f;
        if (myv[u]) {
            int b = __float2int_rd(mybox[u].x) + XOFF;
            b = max(0, min(XBINS - 1, b));
            mybin[u] = b;
            atomicAdd(&hist[b], 1);
        }
    }
    __syncthreads();

    int hv = (t < XBINS) ? hist[t] : 0;
    int inc = blockScanInc(hv, ws);
    if (t < XBINS) sstart[t] = inc - hv;
    if (t == XBINS - 1) g_m[c] = inc;
    __syncthreads();
    for (int b = t; b < XBINS; b += 1024) hist[b] = 0;
    __syncthreads();

#pragma unroll
    for (int u = 0; u < 4; u++) {
        if (myv[u]) {
            int a = t + u * 1024;
            int pos = sstart[mybin[u]] + atomicAdd(&hist[mybin[u]], 1);
            int slot = c * NN + pos;
            float4 b = mybox[u];
            g_sbox[slot] = b;
            g_saux[slot] = make_float2((b.z - b.x + 1.0f) * (b.w - b.y + 1.0f),
                                       __int_as_float(a));
            g_rmin[slot] = a;   // self hit baseline
        }
    }
}

// ---------------- K1: symmetric forward pair scan, 16 sub-threads per anchor ----------------
__global__ __launch_bounds__(512) void k1_pairs() {
    __shared__ float4 tb[K1_SPAN];
    __shared__ float2 ta[K1_SPAN];

    int c  = blockIdx.x >> 7;           // 128 tiles per class
    int S0 = (blockIdx.x & 127) * K1_TILE;
    int m  = g_m[c];
    if (S0 >= m) return;

    for (int k = threadIdx.x; k < K1_SPAN; k += 512) {
        int s = S0 + k;
        if (s < m) {
            tb[k] = g_sbox[c * NN + s];
            ta[k] = g_saux[c * NN + s];
        } else {
            tb[k] = make_float4(3.0e38f, 0.0f, -10.0f, -10.0f); // x1=+inf sentinel
            ta[k] = make_float2(1.0f, __int_as_float(0));
        }
    }
    __syncthreads();

    int ai  = threadIdx.x & (K1_TILE - 1);     // anchor within tile
    int sub = threadIdx.x >> 5;                // 0..15
    int s = S0 + ai;
    if (s >= m) return;

    float4 a    = tb[ai];
    float areaA = ta[ai].x;
    int   origI = __float_as_int(ta[ai].y);
    float limit = a.z + 2.0f;   // (x2_s + 1) + 1px bin-order slop

    for (int ts = ai + 1 + sub; ; ts += K1_SUB) {
        float4 b; float2 ax;
        if (ts < K1_SPAN) {
            b  = tb[ts];
            ax = ta[ts];
        } else {
            int gs = S0 + ts;
            if (gs >= m) break;
            b  = g_sbox[c * NN + gs];
            ax = g_saux[c * NN + gs];
        }
        if (b.x >= limit) break;

        float x1 = fmaxf(a.x, b.x);
        float y1 = fmaxf(a.y, b.y);
        float x2 = fminf(a.z, b.z);
        float y2 = fminf(a.w, b.w);
        float w = x2 - x1 + 1.0f;
        float h = y2 - y1 + 1.0f;
        float inter = w * h;
        float den = areaA + ax.x - inter;
        if (w > 0.0f && h > 0.0f && inter > 0.5f * den) {
            int origJ = __float_as_int(ax.y);
            atomicMin(&g_rmin[c * NN + s], origJ);
            atomicMin(&g_rmin[c * NN + S0 + ts], origI);
        }
    }
}

// ---------------- k5 body: smem-staged keys, 3-pass radix select (one block) ----------------
__device__ __forceinline__ void find_thr(const int* hist, int nbins, int target,
                                         volatile int* out_b, volatile int* out_t,
                                         int* ws) {
    int t = threadIdx.x;
    if (t == 0) { *out_b = 0; *out_t = 0; }
    __syncthreads();
    if (nbins == 2048) {
        int b1 = 2047 - 2 * t;
        int b0 = b1 - 1;
        int h1 = hist[b1], h0 = hist[b0];
        int inc = blockScanInc(h1 + h0, ws);     // suffix sum at b0
        int suf0 = inc;
        int suf1 = inc - h0;
        if (suf1 >= target && suf1 - h1 < target) { *out_b = b1; *out_t = target - (suf1 - h1); }
        if (suf0 >= target && suf0 - h0 < target) { *out_b = b0; *out_t = target - (suf0 - h0); }
    } else {
        int b = 1023 - t;
        int h = hist[b];
        int inc = blockScanInc(h, ws);
        if (inc >= target && inc - h < target) { *out_b = b; *out_t = target - (inc - h); }
    }
    __syncthreads();
}

__device__ void k5_body(int* sm, int* ws, float* __restrict__ out, int out_size) {
    int* hist = sm;                            // [2048] ints
    unsigned* skeys = (unsigned*)(sm + 2048);  // [SKCAP] staged survivor keys
    __shared__ int cb[CC + 1];
    __shared__ int sel[MAXDET];
    __shared__ unsigned arr[MAXDET];
    __shared__ unsigned srt[MAXDET];
    __shared__ volatile int b_sh, t_sh;
    __shared__ int t1_sh, b1_sh, e_sh, gcnt, ecnt;
    __shared__ unsigned pre_sh, K100_sh;

    int t = threadIdx.x;
    if (t == 0) {
        int s = 0;
        for (int c = 0; c < CC; c++) { cb[c] = s; s += g_scount[c]; }
        cb[CC] = s;
        gcnt = 0; ecnt = 0;
    }
    __syncthreads();
    int S = cb[CC];

    // sel[q] = flat id of q-th survivor (class-major, rows ascending)
    if (t < MAXDET && t < S) {
        int c = 0;
        while (c < CC - 1 && t >= cb[c + 1]) c++;
        sel[t] = c * NN + g_srow[c * NN + (t - cb[c])];
    }

    // ---- stage keys into smem (coalesced, once) + zero hist ----
    hist[t] = 0; hist[t + 1024] = 0;
#pragma unroll 1
    for (int c = 0; c < CC; c++) {
        int b0 = cb[c], cnt = cb[c + 1] - b0;
        for (int q = t; q < cnt; q += 1024) {
            int f = b0 + q;
            if (f < SKCAP) skeys[f] = g_skey[c * NN + q];
        }
    }
    __syncthreads();

    auto getkey = [&](int f) -> unsigned {
        if (f < SKCAP) return skeys[f];
        int c = 0;
        while (c < CC - 1 && f >= cb[c + 1]) c++;
        return g_skey[c * NN + (f - cb[c])];
    };

    // ---- radix-select level 1 (top 11 bits) ----
    for (int f = t; f < S; f += 1024) atomicAdd(&hist[getkey(f) >> 21], 1);
    __syncthreads();
    find_thr(hist, 2048, MAXDET, &b_sh, &t_sh, ws);
    if (t == 0) { b1_sh = b_sh; t1_sh = t_sh; }
    __syncthreads();
    unsigned b1 = (unsigned)b1_sh;
    int tgt2 = t1_sh;

    // ---- level 2 (next 11 bits) ----
    hist[t] = 0; hist[t + 1024] = 0;
    __syncthreads();
    for (int f = t; f < S; f += 1024) {
        unsigned k = getkey(f);
        if ((k >> 21) == b1) atomicAdd(&hist[(k >> 10) & 2047u], 1);
    }
    __syncthreads();
    find_thr(hist, 2048, tgt2, &b_sh, &t_sh, ws);
    if (t == 0) { pre_sh = (b1 << 11) | (unsigned)b_sh; e_sh = t_sh; }
    __syncthreads();
    unsigned pre = pre_sh;
    int tgt3 = e_sh;

    // ---- level 3 (low 10 bits) ----
    hist[t] = 0; hist[t + 1024] = 0;
    __syncthreads();
    for (int f = t; f < S; f += 1024) {
        unsigned k = getkey(f);
        if ((k >> 10) == pre) atomicAdd(&hist[k & 1023u], 1);
    }
    __syncthreads();
    find_thr(hist, 1024, tgt3, &b_sh, &t_sh, ws);
    if (t == 0) { K100_sh = (pre << 10) | (unsigned)b_sh; e_sh = t_sh; }
    __syncthreads();
    unsigned K100 = K100_sh;
    int e = e_sh;
    int g = MAXDET - e;

    // ---- collect exactly 100 keys ----
    for (int f = t; f < S; f += 1024) {
        unsigned k = getkey(f);
        if (k > K100) {
            int p = atomicAdd(&gcnt, 1);
            if (p < g) arr[p] = k;
        } else if (k == K100) {
            int p = atomicAdd(&ecnt, 1);
            if (p < e) arr[g + p] = k;
        }
    }
    __syncthreads();

    // ---- rank sort 100 keys descending ----
    int Smin = (S < MAXDET) ? S : MAXDET;
    if (t < Smin) {
        unsigned kt = arr[t];
        int r = 0;
        for (int j = 0; j < Smin; j++) {
            unsigned kj = arr[j];
            r += ((kj > kt) || (kj == kt && j < t)) ? 1 : 0;
        }
        srt[r] = kt;
    }
    __syncthreads();

    // outputs: [scores 100][labels 100][poses 1200][idx 100][boxes 400] = 1900 floats
    if (t < MAXDET) {
        int q = t;
        float osc = -1.0f;
        if (q < S) {
            unsigned u = srt[q];
            u = (u & 0x80000000u) ? (u ^ 0x80000000u) : ~u;
            osc = __uint_as_float(u);
        }
        if (q < out_size) out[q] = osc;
        float lab = (q < S) ? (float)(sel[q] >> 12) : -1.0f;
        if (100 + q < out_size) out[100 + q] = lab;
        float idx = (q < S) ? (float)(sel[q] & (NN - 1)) : -1.0f;
        if (1400 + q < out_size) out[1400 + q] = idx;
    }
    for (int q = t; q < 1200; q += 1024) {
        int k = q / 12, d = q % 12;
        float v = (k < S) ? g_pavg[sel[k] * 12 + d] : -1.0f;
        if (200 + q < out_size) out[200 + q] = v;
    }
    for (int q = t; q < 400; q += 1024) {
        int k = q >> 2, d = q & 3;
        float v = (k < S) ? g_bavg[sel[k] * 4 + d] : -1.0f;
        if (1500 + q < out_size) out[1500 + q] = v;
    }
}

// ---------------- K2: fused values+scan+scatter+top-11+compaction, last block runs k5 ----------------
// dynamic smem layout: scnt[4096] | soff[4096] | cand[4096] (u64)
__global__ __launch_bounds__(1024) void k2_fused(const float* __restrict__ boxes,
                                                 const float* __restrict__ conf,
                                                 const float* __restrict__ poses,
                                                 const float* __restrict__ cls,
                                                 float* __restrict__ out, int out_size) {
    extern __shared__ int sm[];
    int* scnt = sm;                    // counts, later cursors
    int* soff = sm + NN;               // exclusive offsets
    unsigned long long* cand = (unsigned long long*)(sm + 2 * NN);
    __shared__ int ws[32];
    __shared__ int is_last;

    int c = blockIdx.x;
    int t = threadIdx.x;
    int m = g_m[c];

    *(int4*)&scnt[t * 4] = make_int4(0, 0, 0, 0);
    __syncthreads();

    // --- phase 1: per-slot winner value; count per target row (smem atomics) ---
    float vv[4];
    int   vi[4], vr[4];
    bool  has[4];
#pragma unroll
    for (int u = 0; u < 4; u++) {
        has[u] = false;
        int s = t + u * 1024;
        if (s < m) {
            int slot = c * NN + s;
            int r = g_rmin[slot];
            int i = __float_as_int(g_saux[slot].y);
            if (r != i) {
                float4 bi = g_sbox[slot];
                float4 br = *(const float4*)(boxes + (size_t)r * (CC * 4) + c * 4);
                float x1 = fmaxf(bi.x, br.x);
                float y1 = fmaxf(bi.y, br.y);
                float x2 = fminf(bi.z, br.z);
                float y2 = fminf(bi.w, br.w);
                float w = x2 - x1 + 1.0f;
                float h = y2 - y1 + 1.0f;
                float inter = w * h;
                float areaI = (bi.z - bi.x + 1.0f) * (bi.w - bi.y + 1.0f);
                float areaR = (br.z - br.x + 1.0f) * (br.w - br.y + 1.0f);
                float den = areaI + areaR - inter;
                float ov = (den == 0.0f) ? 0.0f : inter / den;
                if (w <= 0.0f || h <= 0.0f) ov = 0.0f;
                float v = (1.0f - ov) * conf[i * CC + c];
                if (v != 0.0f) {
                    vv[u] = v; vi[u] = i; vr[u] = r; has[u] = true;
                    atomicAdd(&scnt[r], 1);
                }
            }
        }
    }
    __syncthreads();

    // --- phase 2: exclusive scan over 4096 row counts ---
    int rcnt[4];
    int run = 0;
    int pre[4];
#pragma unroll
    for (int u = 0; u < 4; u++) {
        rcnt[u] = scnt[t * 4 + u];
        pre[u] = run;
        run += rcnt[u];
    }
    int incv = blockScanInc(run, ws);
    int base = incv - run;
#pragma unroll
    for (int u = 0; u < 4; u++) soff[t * 4 + u] = base + pre[u];
    __syncthreads();
    *(int4*)&scnt[t * 4] = make_int4(0, 0, 0, 0);
    __syncthreads();

    // --- phase 3: scatter candidates into smem CSR ---
#pragma unroll
    for (int u = 0; u < 4; u++) {
        if (has[u]) {
            int r = vr[u];
            int pos = soff[r] + atomicAdd(&scnt[r], 1);
            cand[pos] = ((unsigned long long)__float_as_uint(vv[u]) << 32) | (unsigned)vi[u];
        }
    }
    __syncthreads();

    // --- phase 4: per-row top-11 + averages ---
    int L = min(KH, m);
    bool survu[4];
#pragma unroll
    for (int u = 0; u < 4; u++) {
        int row = t * 4 + u;
        int cnt = rcnt[u];
        int used = 0;
        if (cnt > 0) {
            int off = soff[row];
            unsigned long long b[KH];
#pragma unroll
            for (int p = 0; p < KH; p++) b[p] = ~0ULL;
            for (int q = 0; q < cnt; q++) {
                unsigned long long x = cand[off + q];
#pragma unroll
                for (int p = 0; p < KH; p++) {
                    unsigned long long lo = (b[p] < x) ? b[p] : x;
                    unsigned long long hi = (b[p] < x) ? x : b[p];
                    b[p] = lo;
                    x = hi;
                }
            }
            used = min(min(cnt, KH), L);
            if (used > 0) {
                float ps[12], bs4[4];
#pragma unroll
                for (int d = 0; d < 12; d++) ps[d] = 0.0f;
#pragma unroll
                for (int d = 0; d < 4; d++) bs4[d] = 0.0f;
                for (int q = 0; q < used; q++) {
                    int a = (int)(b[q] & 0xFFFFFFFFu);
                    const float* pp = poses + (size_t)a * (CC * 12) + c * 12;
#pragma unroll
                    for (int d = 0; d < 12; d++) ps[d] += pp[d];
                    const float* bx = boxes + (size_t)a * (CC * 4) + c * 4;
#pragma unroll
                    for (int d = 0; d < 4; d++) bs4[d] += bx[d];
                }
                float den = (float)used;
                int grow = c * NN + row;
#pragma unroll
                for (int d = 0; d < 12; d++) g_pavg[grow * 12 + d] = ps[d] / den;
#pragma unroll
                for (int d = 0; d < 4; d++) g_bavg[grow * 4 + d] = bs4[d] / den;
            }
        }
        survu[u] = (used > 0);
    }
    __syncthreads();

    // --- phase 5: survivor compaction (rows ascending) + key build ---
    int srun = 0;
    int spre[4];
#pragma unroll
    for (int u = 0; u < 4; u++) {
        spre[u] = srun;
        srun += survu[u] ? 1 : 0;
    }
    int sinc = blockScanInc(srun, ws);
    int sbase = sinc - srun;
#pragma unroll
    for (int u = 0; u < 4; u++) {
        if (survu[u]) {
            int row = t * 4 + u;
            int pos = sbase + spre[u];
            g_srow[c * NN + pos] = row;
            unsigned ub = __float_as_uint(cls[row * CC + c]);
            g_skey[c * NN + pos] = ub ^ ((ub & 0x80000000u) ? 0xFFFFFFFFu : 0x80000000u);
        }
    }
    if (t == 1023) g_scount[c] = sinc;
    __syncthreads();

    // --- phase 6: last block runs global selection (threadFenceReduction pattern) ---
    if (t == 0) {
        __threadfence();
        int old = atomicAdd(&g_sync, 1);
        is_last = (old == CC - 1) ? 1 : 0;
        if (is_last) __threadfence();
    }
    __syncthreads();
    if (is_last) {
        k5_body(sm, ws, out, out_size);
    }
}

// ---------------- launcher ----------------
extern "C" void kernel_launch(void* const* d_in, const int* in_sizes, int n_in,
                              void* d_out, int out_size) {
    (void)in_sizes; (void)n_in;
    const float* boxes = (const float*)d_in[1];
    const float* cls   = (const float*)d_in[2];
    const float* poses = (const float*)d_in[3];
    const float* conf  = (const float*)d_in[4];
    float* out = (float*)d_out;

    int smem2 = 2 * NN * (int)sizeof(int) + NN * (int)sizeof(unsigned long long) + 128;
    cudaFuncSetAttribute(k2_fused, cudaFuncAttributeMaxDynamicSharedMemorySize, smem2);

    k0_sort<<<CC, 1024>>>(cls, boxes);
    k1_pairs<<<CC * 128, 512>>>();
    k2_fused<<<CC, 1024, smem2>>>(boxes, conf, poses, cls, out, out_size);
}